// round 1
// baseline (speedup 1.0000x reference)
#include <cuda_runtime.h>
#include <cstdint>

#define NPTS      131072        // 32*64*64 points
#define DIM       64
#define NCODE     512
#define HWSZ      4096          // 64*64
#define OUT_ELEMS 8388608       // 32*64*64*64
#define CTAS      512
#define TPB       256

__device__ float  g_embT[DIM * NCODE];  // [c][j]
__device__ float  g_B[NCODE];           // ||e_j||^2, square-then-add like jnp.sum(emb*emb)
__device__ double g_loss_acc;

// ---------------------------------------------------------------------------
// Prep: transpose emb -> [c][j], compute per-code norms, zero loss accumulator
// ---------------------------------------------------------------------------
__global__ void vq_prep(const float* __restrict__ emb) {
    int j = threadIdx.x;  // 512 threads
    if (j == 0) g_loss_acc = 0.0;
    float s = 0.0f;
#pragma unroll
    for (int c = 0; c < DIM; c++) {
        float v = emb[j * DIM + c];
        g_embT[c * NCODE + j] = v;
        s = __fadd_rn(s, __fmul_rn(v, v));   // square then add (matches jnp)
    }
    g_B[j] = s;
}

// ---------------------------------------------------------------------------
// Main: per point, argmin_j fl(fl(A + B_j) - 2*C_j); write z_q; accumulate loss
// ---------------------------------------------------------------------------
__global__ void __launch_bounds__(TPB, 1)
vq_main(const float* __restrict__ z, float* __restrict__ out_q) {
    extern __shared__ float smem[];
    float* sT = smem;                 // embT [64][512]
    float* sB = smem + DIM * NCODE;   // [512]

    for (int i = threadIdx.x; i < DIM * NCODE; i += TPB) sT[i] = g_embT[i];
    for (int i = threadIdx.x; i < NCODE; i += TPB)       sB[i] = g_B[i];
    __syncthreads();

    int n = blockIdx.x * TPB + threadIdx.x;
    if (n >= NPTS) return;
    int b  = n >> 12;
    int hw = n & (HWSZ - 1);

    // Gather z point: z[b][c][h][w], stride HW per channel (coalesced across warp)
    const float* zp = z + (size_t)b * DIM * HWSZ + hw;
    float zr[DIM];
#pragma unroll
    for (int c = 0; c < DIM; c++) zr[c] = zp[(size_t)c * HWSZ];

    // A = sum(z*z), square-then-add, sequential
    float A = 0.0f;
#pragma unroll
    for (int c = 0; c < DIM; c++) A = __fadd_rn(A, __fmul_rn(zr[c], zr[c]));

    float dmin = __int_as_float(0x7f800000);
    int   imin = 0;

    // Code tiles of 64; f32x2-packed dot products (2 codes per 64-bit accumulator)
#pragma unroll 1
    for (int jt = 0; jt < NCODE; jt += 64) {
        unsigned long long acc[32];
#pragma unroll
        for (int u = 0; u < 32; u++) acc[u] = 0ull;

#pragma unroll
        for (int c = 0; c < DIM; c++) {
            unsigned long long zz;
            asm("mov.b64 %0, {%1, %1};" : "=l"(zz) : "f"(zr[c]));
            const ulonglong2* row =
                reinterpret_cast<const ulonglong2*>(sT + c * NCODE + jt);
#pragma unroll
            for (int u = 0; u < 16; u++) {
                ulonglong2 e2 = row[u];  // 4 consecutive codes, broadcast LDS.128
                asm("fma.rn.f32x2 %0, %1, %2, %0;"
                    : "+l"(acc[2 * u])     : "l"(zz), "l"(e2.x));
                asm("fma.rn.f32x2 %0, %1, %2, %0;"
                    : "+l"(acc[2 * u + 1]) : "l"(zz), "l"(e2.y));
            }
        }

        // Epilogue: d_j = fl(fl(A + B_j) - 2*C_j); ascending j, strict < (first-min)
#pragma unroll
        for (int u = 0; u < 32; u++) {
            float c0, c1;
            asm("mov.b64 {%0, %1}, %2;" : "=f"(c0), "=f"(c1) : "l"(acc[u]));
            int j0 = jt + 2 * u;
            float t0 = __fadd_rn(A, sB[j0]);
            float t1 = __fadd_rn(A, sB[j0 + 1]);
            float d0 = __fadd_rn(t0, -2.0f * c0);   // 2*C exact
            float d1 = __fadd_rn(t1, -2.0f * c1);
            if (d0 < dmin) { dmin = d0; imin = j0; }
            if (d1 < dmin) { dmin = d1; imin = j0 + 1; }
        }
    }

    // Write z_q in [B,C,H,W]; accumulate loss terms in double
    double lsum = 0.0;
#pragma unroll
    for (int c = 0; c < DIM; c++) {
        float q = sT[c * NCODE + imin];
        out_q[((size_t)(b * DIM + c)) * HWSZ + hw] = q;
        float e  = __fadd_rn(q, -zr[c]);
        float sq = __fmul_rn(e, e);
        lsum += (double)sq;
    }

    // warp reduce + atomic
#pragma unroll
    for (int off = 16; off > 0; off >>= 1)
        lsum += __shfl_down_sync(0xffffffffu, lsum, off);
    if ((threadIdx.x & 31) == 0) atomicAdd(&g_loss_acc, lsum);
}

// ---------------------------------------------------------------------------
// Finalize: loss = m + 0.25*m, m = mean of squared diffs
// ---------------------------------------------------------------------------
__global__ void vq_finalize(float* __restrict__ loss_out) {
    float m = (float)(g_loss_acc / (double)OUT_ELEMS);
    loss_out[0] = __fadd_rn(m, __fmul_rn(0.25f, m));
}

// ---------------------------------------------------------------------------
extern "C" void kernel_launch(void* const* d_in, const int* in_sizes, int n_in,
                              void* d_out, int out_size) {
    const float* z   = (const float*)d_in[0];
    const float* emb = (const float*)d_in[1];
    // defensive: swap if metadata order differs
    if (n_in >= 2 && in_sizes[0] == NCODE * DIM && in_sizes[1] == OUT_ELEMS) {
        const float* t = z; z = emb; emb = t;
    }

    float* out   = (float*)d_out;
    float* loss  = nullptr;
    float* qbase = out;
    if (out_size > OUT_ELEMS) {       // (loss, z_q) concatenated, loss first
        loss  = out;
        qbase = out + 1;
    }

    cudaFuncSetAttribute(vq_main, cudaFuncAttributeMaxDynamicSharedMemorySize,
                         (DIM * NCODE + NCODE) * (int)sizeof(float));

    vq_prep<<<1, NCODE>>>(emb);
    vq_main<<<CTAS, TPB, (DIM * NCODE + NCODE) * sizeof(float)>>>(z, qbase);
    if (loss) vq_finalize<<<1, 1>>>(loss);
}

// round 3
// speedup vs baseline: 1.8943x; 1.8943x over previous
#include <cuda_runtime.h>
#include <cuda_bf16.h>
#include <cstdint>

#define NPTS      131072
#define DIM       64
#define NCODE     512
#define HWSZ      4096
#define OUT_ELEMS 8388608
#define TILE_M    128
#define NTILES    1024
#define TPB       256
#define GRID      148
#define THR_M     1e-5f          // m-space gap; d-gap = 2*m-gap <= 2e-5 -> fallback

// ---- smem layout ----
#define OFF_ZT    0              // z tile fp32 [64][128]          32768
#define OFF_AHI   32768          // A_hi bf16 [128][64] SW128      16384
#define OFF_ALO   49152          // A_lo                            16384
#define OFF_BHI   65536          // B_hi bf16 [512][64] SW128      65536
#define OFF_BLO   131072         // B_lo                            65536
#define OFF_SBH   196608         // 0.5*||e||^2 fp32 [512]          2048
#define OFF_SBF   198656         // ||e||^2 fp32 [512]              2048
#define OFF_SAN   200704         // ||z_p||^2 fp32 [128]             512
#define OFF_JB    201216         // int jbest[128]                   512
#define OFF_FLG   201728         // int flag[128]                    512
#define OFF_CNT   202240         // int count
#define OFF_LIST  202248         // int list[128]
#define OFF_KEY   202760         // u64 argmin key
#define SMEM_TOTAL 202768

#define SW128(o)  ((o) ^ (((o) >> 3) & 0x70))

__device__ __align__(16) unsigned char g_bhi[NCODE * 128];
__device__ __align__(16) unsigned char g_blo[NCODE * 128];
__device__ float  g_embT[DIM * NCODE];   // [c][j] fp32 (fallback, coalesced)
__device__ float  g_B[NCODE];
__device__ float  g_Bh[NCODE];
__device__ double g_loss_acc;

__device__ __forceinline__ uint32_t smem_u32(const void* p) {
    uint32_t a;
    asm("{ .reg .u64 t; cvta.to.shared.u64 t, %1; cvt.u32.u64 %0, t; }"
        : "=r"(a) : "l"(p));
    return a;
}
#define LDSM4(R, addr)                                                        \
    asm volatile("ldmatrix.sync.aligned.m8n8.x4.shared.b16 {%0,%1,%2,%3}, [%4];" \
                 : "=r"((R)[0]), "=r"((R)[1]), "=r"((R)[2]), "=r"((R)[3])     \
                 : "r"(addr))
#define MMA_BF16(C, A, b0, b1)                                                \
    asm volatile("mma.sync.aligned.m16n8k16.row.col.f32.bf16.bf16.f32 "      \
                 "{%0,%1,%2,%3},{%4,%5,%6,%7},{%8,%9},{%0,%1,%2,%3};"        \
                 : "+f"((C)[0]), "+f"((C)[1]), "+f"((C)[2]), "+f"((C)[3])     \
                 : "r"((A)[0]), "r"((A)[1]), "r"((A)[2]), "r"((A)[3]),        \
                   "r"(b0), "r"(b1))

// ---------------------------------------------------------------- prep
__global__ void vq_prep(const float* __restrict__ emb) {
    __shared__ float row[DIM];
    int j = blockIdx.x, c = threadIdx.x;
    float v = emb[j * DIM + c];
    row[c] = v;
    g_embT[c * NCODE + j] = v;
    __nv_bfloat16 h = __float2bfloat16(v);
    float hf = __bfloat162float(h);
    __nv_bfloat16 l = __float2bfloat16(v - hf);
    uint32_t sw = SW128((uint32_t)(j * 128 + c * 2));
    *(__nv_bfloat16*)(g_bhi + sw) = h;
    *(__nv_bfloat16*)(g_blo + sw) = l;
    __syncthreads();
    if (c == 0) {
        float s = 0.0f;
        for (int k = 0; k < DIM; k++) s = __fadd_rn(s, __fmul_rn(row[k], row[k]));
        g_B[j]  = s;
        g_Bh[j] = 0.5f * s;
        if (j == 0) g_loss_acc = 0.0;
    }
}

// ---------------------------------------------------------------- main
__global__ void __launch_bounds__(TPB, 1)
vq_main(const float* __restrict__ z, const float* __restrict__ emb,
        float* __restrict__ outq) {
    extern __shared__ char smem[];
    const uint32_t sbase = smem_u32(smem);
    float* zt   = (float*)(smem + OFF_ZT);
    float* sBh  = (float*)(smem + OFF_SBH);
    float* sBf  = (float*)(smem + OFF_SBF);
    float* sAn  = (float*)(smem + OFF_SAN);
    int*   jb   = (int*)(smem + OFF_JB);
    int*   flg  = (int*)(smem + OFF_FLG);
    int*   cnt  = (int*)(smem + OFF_CNT);
    int*   list = (int*)(smem + OFF_LIST);
    unsigned long long* key = (unsigned long long*)(smem + OFF_KEY);

    const int tid = threadIdx.x, wid = tid >> 5, lane = tid & 31;

    // Stage B tiles + norms
    {
        const int4* sh = (const int4*)g_bhi;
        const int4* sl = (const int4*)g_blo;
        int4* dh = (int4*)(smem + OFF_BHI);
        int4* dl = (int4*)(smem + OFF_BLO);
        for (int i = tid; i < NCODE * 128 / 16; i += TPB) { dh[i] = sh[i]; dl[i] = sl[i]; }
        for (int i = tid; i < NCODE; i += TPB) { sBh[i] = g_Bh[i]; sBf[i] = g_B[i]; }
    }

    // ldmatrix lane geometry
    const int mi  = lane >> 3, r8 = lane & 7;
    const int lam = lane & 3,  g  = lane >> 2;
    const uint32_t m0 = wid * 16;
    const uint32_t a_row  = m0 + ((mi & 1) << 3) + r8;      // A matrix row
    const uint32_t a_kcol = (mi >> 1) << 3;                 // A k sub-col
    const uint32_t b_crow = ((mi >> 1) << 3) + r8;          // B code row (in 16)
    const uint32_t b_kcol = (mi & 1) << 3;                  // B k sub-col

    for (int t = blockIdx.x; t < NTILES; t += GRID) {
        const int b   = t >> 5;
        const int hw0 = (t & 31) << 7;
        const float* zsrc = z + ((size_t)b << 18) + hw0;

        __syncthreads();

        // ---- load z tile [64][128] fp32 ----
        for (int f = tid; f < 2048; f += TPB) {
            int row = f >> 5, col = f & 31;
            ((float4*)zt)[f] = ((const float4*)(zsrc + (size_t)row * HWSZ))[col];
        }
        __syncthreads();

        // ---- convert to A_hi/A_lo (SW128), per-point norm ----
        if (tid < TILE_M) {
            float A = 0.0f;
#pragma unroll
            for (int c = 0; c < DIM; c += 2) {
                float v0 = zt[c * TILE_M + tid];
                float v1 = zt[(c + 1) * TILE_M + tid];
                A = __fadd_rn(A, __fmul_rn(v0, v0));
                A = __fadd_rn(A, __fmul_rn(v1, v1));
                __nv_bfloat16 h0 = __float2bfloat16(v0);
                __nv_bfloat16 h1 = __float2bfloat16(v1);
                __nv_bfloat16 l0 = __float2bfloat16(v0 - __bfloat162float(h0));
                __nv_bfloat16 l1 = __float2bfloat16(v1 - __bfloat162float(h1));
                uint32_t hp = (uint32_t)__bfloat16_as_ushort(h0) |
                              ((uint32_t)__bfloat16_as_ushort(h1) << 16);
                uint32_t lp = (uint32_t)__bfloat16_as_ushort(l0) |
                              ((uint32_t)__bfloat16_as_ushort(l1) << 16);
                uint32_t sw = SW128((uint32_t)(tid * 128 + c * 2));
                *(uint32_t*)(smem + OFF_AHI + sw) = hp;
                *(uint32_t*)(smem + OFF_ALO + sw) = lp;
            }
            sAn[tid] = A;
        }
        if (tid == 0) *cnt = 0;
        __syncthreads();

        // ---- preload A fragments (reused over all 16 N-chunks) ----
        uint32_t Ahi[4][4], Alo[4][4];
#pragma unroll
        for (int kk = 0; kk < 4; kk++) {
            uint32_t off = a_row * 128 + (kk * 16 + a_kcol) * 2;
            uint32_t sw  = SW128(off);
            LDSM4(Ahi[kk], sbase + OFF_AHI + sw);
            LDSM4(Alo[kk], sbase + OFF_ALO + sw);
        }

        // trackers: rows g and g+8 of this warp's 16 points
        float v1a = -3.0e38f, v2a = -3.0e38f; int j1a = 0;
        float v1b = -3.0e38f, v2b = -3.0e38f; int j1b = 0;

#pragma unroll 1
        for (int nc = 0; nc < 16; nc++) {
            const int n0 = nc * 32;
            float C[4][4];
#pragma unroll
            for (int nt = 0; nt < 4; nt++)
#pragma unroll
                for (int u = 0; u < 4; u++) C[nt][u] = 0.0f;

#pragma unroll
            for (int kk = 0; kk < 4; kk++) {
                uint32_t bh[8], bl[8];
                uint32_t o0 = (n0 + b_crow) * 128 + (kk * 16 + b_kcol) * 2;
                uint32_t o1 = (n0 + 16 + b_crow) * 128 + (kk * 16 + b_kcol) * 2;
                uint32_t s0 = SW128(o0), s1 = SW128(o1);
                LDSM4(bh + 0, sbase + OFF_BHI + s0);
                LDSM4(bl + 0, sbase + OFF_BLO + s0);
                LDSM4(bh + 4, sbase + OFF_BHI + s1);
                LDSM4(bl + 4, sbase + OFF_BLO + s1);
#pragma unroll
                for (int nt = 0; nt < 4; nt++) {
                    int ix = nt * 2;
                    MMA_BF16(C[nt], Ahi[kk], bh[ix], bh[ix + 1]);
                    MMA_BF16(C[nt], Ahi[kk], bl[ix], bl[ix + 1]);
                    MMA_BF16(C[nt], Alo[kk], bh[ix], bh[ix + 1]);
                }
            }
            // epilogue: m = C - B/2, top-2 per row
#pragma unroll
            for (int nt = 0; nt < 4; nt++) {
                int jc = n0 + nt * 8 + (lam << 1);
                float2 bh2 = *(const float2*)(smem + OFF_SBH + jc * 4);
                float m00 = C[nt][0] - bh2.x;
                float m01 = C[nt][1] - bh2.y;
                float m10 = C[nt][2] - bh2.x;
                float m11 = C[nt][3] - bh2.y;
                if (m00 > v1a) { v2a = v1a; v1a = m00; j1a = jc; }
                else if (m00 > v2a) v2a = m00;
                if (m01 > v1a) { v2a = v1a; v1a = m01; j1a = jc + 1; }
                else if (m01 > v2a) v2a = m01;
                if (m10 > v1b) { v2b = v1b; v1b = m10; j1b = jc; }
                else if (m10 > v2b) v2b = m10;
                if (m11 > v1b) { v2b = v1b; v1b = m11; j1b = jc + 1; }
                else if (m11 > v2b) v2b = m11;
            }
        }

        // merge top-2 across the quad (lanes sharing a row)
#pragma unroll
        for (int x = 1; x < 4; x <<= 1) {
            float ov1 = __shfl_xor_sync(0xffffffffu, v1a, x);
            int   oj1 = __shfl_xor_sync(0xffffffffu, j1a, x);
            float ov2 = __shfl_xor_sync(0xffffffffu, v2a, x);
            bool bw = (ov1 > v1a) || (ov1 == v1a && oj1 < j1a);
            float nv2 = bw ? fmaxf(v1a, ov2) : fmaxf(ov1, v2a);
            if (bw) { v1a = ov1; j1a = oj1; }
            v2a = nv2;
            ov1 = __shfl_xor_sync(0xffffffffu, v1b, x);
            oj1 = __shfl_xor_sync(0xffffffffu, j1b, x);
            ov2 = __shfl_xor_sync(0xffffffffu, v2b, x);
            bw = (ov1 > v1b) || (ov1 == v1b && oj1 < j1b);
            nv2 = bw ? fmaxf(v1b, ov2) : fmaxf(ov1, v2b);
            if (bw) { v1b = ov1; j1b = oj1; }
            v2b = nv2;
        }
        if (lam == 0) {
            int p0 = m0 + g, p1 = m0 + g + 8;
            jb[p0]  = j1a; flg[p0] = (v1a - v2a) <= THR_M;
            jb[p1]  = j1b; flg[p1] = (v1b - v2b) <= THR_M;
        }
        __syncthreads();

        // ---- exact fp32 fallback for ambiguous points (rare) ----
        if (tid < TILE_M && flg[tid]) { int pos = atomicAdd(cnt, 1); list[pos] = tid; }
        __syncthreads();
        int nf = *cnt;
        for (int i = 0; i < nf; i++) {
            int p = list[i];
            if (tid == 0) *key = ~0ull;
            __syncthreads();
            float Ap = sAn[p];
#pragma unroll 1
            for (int jj = tid; jj < NCODE; jj += TPB) {
                float Cx = 0.0f;
#pragma unroll
                for (int c = 0; c < DIM; c++)
                    Cx = __fmaf_rn(zt[c * TILE_M + p], g_embT[c * NCODE + jj], Cx);
                float tt = __fadd_rn(Ap, sBf[jj]);
                float dd = __fadd_rn(tt, -2.0f * Cx);
                unsigned du = __float_as_uint(dd);
                unsigned od = (du & 0x80000000u) ? ~du : (du ^ 0x80000000u);
                atomicMin(key, ((unsigned long long)od << 32) | (unsigned)jj);
            }
            __syncthreads();
            if (tid == 0) jb[p] = (int)(*key & 0xffffffffu);
        }
        __syncthreads();

        // ---- output + loss ----
        if (tid < TILE_M) {
            int jq = jb[tid];
            const float* erow = emb + jq * DIM;
            float* obase = outq + ((size_t)b << 18) + hw0 + tid;
            double lsum = 0.0;
#pragma unroll
            for (int c = 0; c < DIM; c++) {
                float q = __ldg(erow + c);
                obase[(size_t)c * HWSZ] = q;
                float e = __fadd_rn(q, -zt[c * TILE_M + tid]);
                lsum += (double)__fmul_rn(e, e);
            }
#pragma unroll
            for (int off = 16; off > 0; off >>= 1)
                lsum += __shfl_down_sync(0xffffffffu, lsum, off);
            if (lane == 0) atomicAdd(&g_loss_acc, lsum);
        }
    }
}

// ---------------------------------------------------------------- finalize
__global__ void vq_finalize(float* __restrict__ loss_out) {
    float m = (float)(g_loss_acc / (double)OUT_ELEMS);
    loss_out[0] = __fadd_rn(m, __fmul_rn(0.25f, m));
}

// ----------------------------------------------------------------
extern "C" void kernel_launch(void* const* d_in, const int* in_sizes, int n_in,
                              void* d_out, int out_size) {
    const float* z   = (const float*)d_in[0];
    const float* emb = (const float*)d_in[1];
    if (n_in >= 2 && in_sizes[0] == NCODE * DIM && in_sizes[1] == OUT_ELEMS) {
        const float* t = z; z = emb; emb = t;
    }

    float* out   = (float*)d_out;
    float* loss  = nullptr;
    float* qbase = out;
    if (out_size > OUT_ELEMS) { loss = out; qbase = out + 1; }

    cudaFuncSetAttribute(vq_main, cudaFuncAttributeMaxDynamicSharedMemorySize,
                         SMEM_TOTAL);

    vq_prep<<<NCODE, DIM>>>(emb);
    vq_main<<<GRID, TPB, SMEM_TOTAL>>>(z, emb, qbase);
    if (loss) vq_finalize<<<1, 1>>>(loss);
}